// round 2
// baseline (speedup 1.0000x reference)
#include <cuda_runtime.h>
#include <cstdint>
#include <cstddef>
#include <math.h>

#define B_   32
#define T_   1024
#define DIN_ 512
#define A_   256
#define H_   512
#define V_   41
#define G_   1536          // 3*H
#define M_   (B_ * T_)     // 32768 rows

// ---------------- static device scratch (no runtime allocation) ----------------
__device__ float g_a [(size_t)M_ * A_];   // adapter output
__device__ float g_gx[(size_t)M_ * G_];   // input-to-hidden gate preactivations
__device__ float g_hs[(size_t)M_ * H_];   // hidden states for all (b,t)
__device__ float g_hbuf[2][H_ * B_];      // double-buffered h, layout [k*32 + b]
__device__ unsigned g_cnt;                // grid barrier arrival counter (returns to 0)
__device__ unsigned g_gen;                // grid barrier generation (monotonic)

// ==============================================================================
// Generic fp32 GEMM:  C[M,N] = A[M,K] @ W[N,K]^T + bias[N]
// 128x128x16 tiles, 256 threads, 8x8 register microtiles.
// Requires M % 128 == 0, K % 16 == 0. N is guarded.
// ==============================================================================
#define GBM 128
#define GBN 128
#define GBK 16
#define GPAD 132

__global__ __launch_bounds__(256) void gemm_bias_kernel(
    const float* __restrict__ A, const float* __restrict__ W,
    const float* __restrict__ bias, float* __restrict__ C,
    int M, int N, int K)
{
    __shared__ float As[GBK][GPAD];
    __shared__ float Ws[GBK][GPAD];

    const int tid = threadIdx.x;
    const int m0 = blockIdx.y * GBM;
    const int n0 = blockIdx.x * GBN;
    const int tx = tid & 15, ty = tid >> 4;
    const int cm = ty * 8, cn = tx * 8;

    const int lrow = tid >> 2;       // 0..63
    const int lc4  = (tid & 3) * 4;  // 0,4,8,12

    float acc[8][8];
#pragma unroll
    for (int i = 0; i < 8; ++i)
#pragma unroll
        for (int j = 0; j < 8; ++j) acc[i][j] = 0.f;

    for (int k0 = 0; k0 < K; k0 += GBK) {
        float4 a0 = *(const float4*)&A[(size_t)(m0 + lrow)      * K + k0 + lc4];
        float4 a1 = *(const float4*)&A[(size_t)(m0 + lrow + 64) * K + k0 + lc4];
        int na = n0 + lrow, nb = n0 + lrow + 64;
        float4 w0 = (na < N) ? *(const float4*)&W[(size_t)na * K + k0 + lc4]
                             : make_float4(0.f, 0.f, 0.f, 0.f);
        float4 w1 = (nb < N) ? *(const float4*)&W[(size_t)nb * K + k0 + lc4]
                             : make_float4(0.f, 0.f, 0.f, 0.f);
        __syncthreads();
        As[lc4 + 0][lrow] = a0.x; As[lc4 + 1][lrow] = a0.y;
        As[lc4 + 2][lrow] = a0.z; As[lc4 + 3][lrow] = a0.w;
        As[lc4 + 0][lrow + 64] = a1.x; As[lc4 + 1][lrow + 64] = a1.y;
        As[lc4 + 2][lrow + 64] = a1.z; As[lc4 + 3][lrow + 64] = a1.w;
        Ws[lc4 + 0][lrow] = w0.x; Ws[lc4 + 1][lrow] = w0.y;
        Ws[lc4 + 2][lrow] = w0.z; Ws[lc4 + 3][lrow] = w0.w;
        Ws[lc4 + 0][lrow + 64] = w1.x; Ws[lc4 + 1][lrow + 64] = w1.y;
        Ws[lc4 + 2][lrow + 64] = w1.z; Ws[lc4 + 3][lrow + 64] = w1.w;
        __syncthreads();

#pragma unroll
        for (int k = 0; k < GBK; ++k) {
            float ra[8], rb[8];
            *(float4*)&ra[0] = *(const float4*)&As[k][cm];
            *(float4*)&ra[4] = *(const float4*)&As[k][cm + 4];
            *(float4*)&rb[0] = *(const float4*)&Ws[k][cn];
            *(float4*)&rb[4] = *(const float4*)&Ws[k][cn + 4];
#pragma unroll
            for (int i = 0; i < 8; ++i)
#pragma unroll
                for (int j = 0; j < 8; ++j)
                    acc[i][j] = fmaf(ra[i], rb[j], acc[i][j]);
        }
    }

    if ((N & 3) == 0 && n0 + cn + 7 < N) {
        // vectorized epilogue (N multiple of 4 keeps 16B alignment)
        float4 bv0 = *(const float4*)&bias[n0 + cn];
        float4 bv1 = *(const float4*)&bias[n0 + cn + 4];
#pragma unroll
        for (int i = 0; i < 8; ++i) {
            size_t base = (size_t)(m0 + cm + i) * N + n0 + cn;
            float4 c0 = make_float4(acc[i][0] + bv0.x, acc[i][1] + bv0.y,
                                    acc[i][2] + bv0.z, acc[i][3] + bv0.w);
            float4 c1 = make_float4(acc[i][4] + bv1.x, acc[i][5] + bv1.y,
                                    acc[i][6] + bv1.z, acc[i][7] + bv1.w);
            *(float4*)&C[base]     = c0;
            *(float4*)&C[base + 4] = c1;
        }
    } else {
#pragma unroll
        for (int i = 0; i < 8; ++i) {
            int mrow = m0 + cm + i;
#pragma unroll
            for (int j = 0; j < 8; ++j) {
                int n = n0 + cn + j;
                if (n < N) C[(size_t)mrow * N + n] = acc[i][j] + bias[n];
            }
        }
    }
}

// ==============================================================================
// GRU recurrence: persistent kernel, 128 co-resident CTAs, grid barrier per step.
// CTA jg owns hidden units j0..j0+3 (12 gate rows). W_hh slice resident in smem.
// h broadcast each step via cp.async.cg (L2-coherent; bypasses stale L1).
// 192 threads = 6 warps: (gate 0..2) x (k-half 0..1), lane = batch index.
// ==============================================================================
#define NBLK 128
#define RT   192

// dynamic smem layout (floats): h_sh[16384] | w_sh[6144] | part[768]
#define SM_H    0
#define SM_W    16384
#define SM_PART (16384 + 6144)
#define SMEM_FLOATS (16384 + 6144 + 768)
#define SMEM_BYTES  (SMEM_FLOATS * 4)

__device__ __forceinline__ void cp_async16(float* s, const float* g) {
    unsigned sa = (unsigned)__cvta_generic_to_shared(s);
    asm volatile("cp.async.cg.shared.global [%0], [%1], 16;" :: "r"(sa), "l"(g));
}

__global__ __launch_bounds__(RT, 1) void gru_kernel(
    const float* __restrict__ gx,
    const float* __restrict__ W_hh,
    const float* __restrict__ b_hh)
{
    extern __shared__ float smem[];
    float* h_sh = smem + SM_H;
    float* w_sh = smem + SM_W;
    float* part = smem + SM_PART;

    const int tid  = threadIdx.x;
    const int j0   = blockIdx.x * 4;
    const int warp = tid >> 5, lane = tid & 31;
    const int g    = warp >> 1, half = warp & 1;
    const int k0h  = half * 256;

    // Load W_hh slice once: w_sh[(g*512+k)*4+j] = W_hh[g*H + j0+j][k]
    for (int idx = tid; idx < 6144; idx += RT) {
        int j = idx & 3, k = (idx >> 2) & 511, gg = idx >> 11;
        w_sh[idx] = W_hh[(size_t)(gg * H_ + j0 + j) * H_ + k];
    }
    // h0 = 0
    for (int idx = tid; idx < H_ * B_; idx += RT) h_sh[idx] = 0.f;

    // per-thread gate-phase constants (tid < 128: j=jj, b=bb)
    const int jj = tid >> 5, bb = tid & 31;
    float bhr = 0.f, bhz = 0.f, bhn = 0.f;
    if (tid < 128) {
        bhr = b_hh[0 * H_ + j0 + jj];
        bhz = b_hh[1 * H_ + j0 + jj];
        bhn = b_hh[2 * H_ + j0 + jj];
    }
    __syncthreads();

    for (int t = 0; t < T_; ++t) {
        // stage h_t from the double buffer (t=0 already has zeros in smem)
        if (t > 0) {
            const float* src = g_hbuf[t & 1];
            for (int off = tid * 4; off < H_ * B_; off += RT * 4)
                cp_async16(h_sh + off, src + off);
            asm volatile("cp.async.commit_group;" ::: "memory");
        }
        // prefetch this step's gx values (overlaps cp.async wait)
        float gxr = 0.f, gxz = 0.f, gxn = 0.f;
        if (tid < 128) {
            const float* row = gx + ((size_t)bb * T_ + t) * G_;
            gxr = row[0 * H_ + j0 + jj];
            gxz = row[1 * H_ + j0 + jj];
            gxn = row[2 * H_ + j0 + jj];
        }
        if (t > 0) asm volatile("cp.async.wait_group 0;" ::: "memory");
        __syncthreads();

        // partial dot products: gh[g][j0+j][b] over this warp's k-half
        const float* wp = w_sh + (g * 512 + k0h) * 4;
        const float* hp = h_sh + k0h * 32 + lane;
        float a0 = 0.f, a1 = 0.f, a2 = 0.f, a3 = 0.f;
#pragma unroll 8
        for (int k = 0; k < 256; ++k) {
            float  hv = hp[k * 32];
            float4 w4 = *(const float4*)(wp + k * 4);
            a0 = fmaf(hv, w4.x, a0);
            a1 = fmaf(hv, w4.y, a1);
            a2 = fmaf(hv, w4.z, a2);
            a3 = fmaf(hv, w4.w, a3);
        }
        {
            float* pp = part + ((g * 2 + half) * 4) * 32 + lane;
            pp[0 * 32] = a0; pp[1 * 32] = a1; pp[2 * 32] = a2; pp[3 * 32] = a3;
        }
        float hold = (tid < 128) ? h_sh[(j0 + jj) * 32 + bb] : 0.f;
        __syncthreads();

        // gate math + h update (threads 0..127: one (j,b) each)
        if (tid < 128) {
            float ghr = part[((0 * 2 + 0) * 4 + jj) * 32 + bb]
                      + part[((0 * 2 + 1) * 4 + jj) * 32 + bb] + bhr;
            float ghz = part[((1 * 2 + 0) * 4 + jj) * 32 + bb]
                      + part[((1 * 2 + 1) * 4 + jj) * 32 + bb] + bhz;
            float ghn = part[((2 * 2 + 0) * 4 + jj) * 32 + bb]
                      + part[((2 * 2 + 1) * 4 + jj) * 32 + bb] + bhn;
            float r  = 1.f / (1.f + expf(-(gxr + ghr)));
            float z  = 1.f / (1.f + expf(-(gxz + ghz)));
            float n  = tanhf(gxn + r * ghn);
            float hn = (1.f - z) * n + z * hold;
            g_hbuf[(t + 1) & 1][(j0 + jj) * 32 + bb] = hn;
            g_hs[((size_t)bb * T_ + t) * H_ + j0 + jj] = hn;
        }

        // ---- grid barrier (sense via monotonically increasing generation) ----
        __syncthreads();
        if (tid == 0) {
            __threadfence();
            unsigned old  = *(volatile unsigned*)&g_gen;
            unsigned tick = atomicAdd(&g_cnt, 1u);
            if (tick == NBLK - 1) {
                atomicExch(&g_cnt, 0u);
                __threadfence();
                atomicExch(&g_gen, old + 1u);
            } else {
                while (*(volatile unsigned*)&g_gen == old) { __nanosleep(40); }
            }
        }
        __syncthreads();
    }
}

// ==============================================================================
// In-place log_softmax over V=41 columns; one warp per row.
// ==============================================================================
__global__ __launch_bounds__(256) void lsm_kernel(float* __restrict__ out, int Mrows)
{
    int row  = blockIdx.x * 8 + (threadIdx.x >> 5);
    int lane = threadIdx.x & 31;
    if (row >= Mrows) return;
    float* p = out + (size_t)row * V_;

    float v0 = (lane      < V_) ? p[lane]      : -INFINITY;
    float v1 = (lane + 32 < V_) ? p[lane + 32] : -INFINITY;
    float m = fmaxf(v0, v1);
#pragma unroll
    for (int o = 16; o > 0; o >>= 1) m = fmaxf(m, __shfl_xor_sync(0xFFFFFFFFu, m, o));
    float s = 0.f;
    if (lane      < V_) s += expf(v0 - m);
    if (lane + 32 < V_) s += expf(v1 - m);
#pragma unroll
    for (int o = 16; o > 0; o >>= 1) s += __shfl_xor_sync(0xFFFFFFFFu, s, o);
    float l = m + logf(s);
    if (lane      < V_) p[lane]      = v0 - l;
    if (lane + 32 < V_) p[lane + 32] = v1 - l;
}

// ==============================================================================
// Host launcher
// ==============================================================================
extern "C" void kernel_launch(void* const* d_in, const int* in_sizes, int n_in,
                              void* d_out, int out_size)
{
    const float* x     = (const float*)d_in[0];
    const float* W_ad  = (const float*)d_in[1];
    const float* b_ad  = (const float*)d_in[2];
    const float* W_ih  = (const float*)d_in[3];
    const float* W_hh  = (const float*)d_in[4];
    const float* b_ih  = (const float*)d_in[5];
    const float* b_hh  = (const float*)d_in[6];
    const float* W_fc  = (const float*)d_in[7];
    const float* b_fc  = (const float*)d_in[8];
    float* out = (float*)d_out;

    float *pa, *pgx, *phs;
    cudaGetSymbolAddress((void**)&pa,  g_a);
    cudaGetSymbolAddress((void**)&pgx, g_gx);
    cudaGetSymbolAddress((void**)&phs, g_hs);

    cudaFuncSetAttribute(gru_kernel, cudaFuncAttributeMaxDynamicSharedMemorySize,
                         SMEM_BYTES);

    // 1) adapter: a = x @ W_ad^T + b_ad        (M x 256, K=512)
    gemm_bias_kernel<<<dim3(A_ / GBN, M_ / GBM), 256>>>(x, W_ad, b_ad, pa, M_, A_, DIN_);
    // 2) gates:   gx = a @ W_ih^T + b_ih       (M x 1536, K=256)
    gemm_bias_kernel<<<dim3(G_ / GBN, M_ / GBM), 256>>>(pa, W_ih, b_ih, pgx, M_, G_, A_);
    // 3) GRU recurrence (persistent, grid barrier per step)
    gru_kernel<<<NBLK, RT, SMEM_BYTES>>>(pgx, W_hh, b_hh);
    // 4) logits into d_out: hs @ W_fc^T + b_fc (M x 41, K=512)
    gemm_bias_kernel<<<dim3(1, M_ / GBM), 256>>>(phs, W_fc, b_fc, out, M_, V_, H_);
    // 5) in-place log_softmax
    lsm_kernel<<<M_ / 8, 256>>>(out, M_);
}

// round 4
// speedup vs baseline: 1.2091x; 1.2091x over previous
#include <cuda_runtime.h>
#include <cstdint>
#include <cstddef>
#include <math.h>

#define B_   32
#define T_   1024
#define DIN_ 512
#define A_   256
#define H_   512
#define V_   41
#define G_   1536          // 3*H
#define M_   (B_ * T_)     // 32768 rows

// ---------------- static device scratch (no runtime allocation) ----------------
__device__ float g_a [(size_t)M_ * A_];   // adapter output
__device__ float g_gx[(size_t)M_ * G_];   // input-to-hidden gate preactivations
__device__ float g_hs[(size_t)M_ * H_];   // hidden states for all (b,t)
__device__ float g_hbuf[2][H_ * B_];      // double-buffered h, layout [k*32 + b]
__device__ unsigned g_cnt;                // grid barrier arrival counter (returns to 0)
__device__ unsigned g_gen;                // grid barrier generation (monotonic)

// ==============================================================================
// Generic fp32 GEMM:  C[M,N] = A[M,K] @ W[N,K]^T + bias[N]
// 128x128x16 tiles, 256 threads, 8x8 register microtiles.
// ==============================================================================
#define GBM 128
#define GBN 128
#define GBK 16
#define GPAD 132

__global__ __launch_bounds__(256) void gemm_bias_kernel(
    const float* __restrict__ A, const float* __restrict__ W,
    const float* __restrict__ bias, float* __restrict__ C,
    int M, int N, int K)
{
    __shared__ float As[GBK][GPAD];
    __shared__ float Ws[GBK][GPAD];

    const int tid = threadIdx.x;
    const int m0 = blockIdx.y * GBM;
    const int n0 = blockIdx.x * GBN;
    const int tx = tid & 15, ty = tid >> 4;
    const int cm = ty * 8, cn = tx * 8;

    const int lrow = tid >> 2;       // 0..63
    const int lc4  = (tid & 3) * 4;  // 0,4,8,12

    float acc[8][8];
#pragma unroll
    for (int i = 0; i < 8; ++i)
#pragma unroll
        for (int j = 0; j < 8; ++j) acc[i][j] = 0.f;

    for (int k0 = 0; k0 < K; k0 += GBK) {
        float4 a0 = *(const float4*)&A[(size_t)(m0 + lrow)      * K + k0 + lc4];
        float4 a1 = *(const float4*)&A[(size_t)(m0 + lrow + 64) * K + k0 + lc4];
        int na = n0 + lrow, nb = n0 + lrow + 64;
        float4 w0 = (na < N) ? *(const float4*)&W[(size_t)na * K + k0 + lc4]
                             : make_float4(0.f, 0.f, 0.f, 0.f);
        float4 w1 = (nb < N) ? *(const float4*)&W[(size_t)nb * K + k0 + lc4]
                             : make_float4(0.f, 0.f, 0.f, 0.f);
        __syncthreads();
        As[lc4 + 0][lrow] = a0.x; As[lc4 + 1][lrow] = a0.y;
        As[lc4 + 2][lrow] = a0.z; As[lc4 + 3][lrow] = a0.w;
        As[lc4 + 0][lrow + 64] = a1.x; As[lc4 + 1][lrow + 64] = a1.y;
        As[lc4 + 2][lrow + 64] = a1.z; As[lc4 + 3][lrow + 64] = a1.w;
        Ws[lc4 + 0][lrow] = w0.x; Ws[lc4 + 1][lrow] = w0.y;
        Ws[lc4 + 2][lrow] = w0.z; Ws[lc4 + 3][lrow] = w0.w;
        Ws[lc4 + 0][lrow + 64] = w1.x; Ws[lc4 + 1][lrow + 64] = w1.y;
        Ws[lc4 + 2][lrow + 64] = w1.z; Ws[lc4 + 3][lrow + 64] = w1.w;
        __syncthreads();

#pragma unroll
        for (int k = 0; k < GBK; ++k) {
            float ra[8], rb[8];
            *(float4*)&ra[0] = *(const float4*)&As[k][cm];
            *(float4*)&ra[4] = *(const float4*)&As[k][cm + 4];
            *(float4*)&rb[0] = *(const float4*)&Ws[k][cn];
            *(float4*)&rb[4] = *(const float4*)&Ws[k][cn + 4];
#pragma unroll
            for (int i = 0; i < 8; ++i)
#pragma unroll
                for (int j = 0; j < 8; ++j)
                    acc[i][j] = fmaf(ra[i], rb[j], acc[i][j]);
        }
    }

    if ((N & 3) == 0 && n0 + cn + 7 < N) {
        float4 bv0 = *(const float4*)&bias[n0 + cn];
        float4 bv1 = *(const float4*)&bias[n0 + cn + 4];
#pragma unroll
        for (int i = 0; i < 8; ++i) {
            size_t base = (size_t)(m0 + cm + i) * N + n0 + cn;
            float4 c0 = make_float4(acc[i][0] + bv0.x, acc[i][1] + bv0.y,
                                    acc[i][2] + bv0.z, acc[i][3] + bv0.w);
            float4 c1 = make_float4(acc[i][4] + bv1.x, acc[i][5] + bv1.y,
                                    acc[i][6] + bv1.z, acc[i][7] + bv1.w);
            *(float4*)&C[base]     = c0;
            *(float4*)&C[base + 4] = c1;
        }
    } else {
#pragma unroll
        for (int i = 0; i < 8; ++i) {
            int mrow = m0 + cm + i;
#pragma unroll
            for (int j = 0; j < 8; ++j) {
                int n = n0 + cn + j;
                if (n < N) C[(size_t)mrow * N + n] = acc[i][j] + bias[n];
            }
        }
    }
}

// ==============================================================================
// GRU recurrence v2: 128 CTAs x 4 units, 8 warps x 64-wide K-slices.
// Each warp: stages ITS OWN K-slice of h (warp-local cp.async group), then
// computes all 12 gate-rows x 32 batch over that slice.
// smem ratio: 4 wavefronts per 12 FFMA. Grid barrier: acquire-spin, no sleep.
// ==============================================================================
#define NBLK 128
#define RT2  256

// dynamic smem (floats): h_sh[16384] | w_sh[6144] | part[3072]
#define SM2_W    16384
#define SM2_PART (16384 + 6144)
#define SMEM2_FLOATS (16384 + 6144 + 3072)
#define SMEM2_BYTES  (SMEM2_FLOATS * 4)

__device__ __forceinline__ void cp_async16(float* s, const float* g) {
    unsigned sa = (unsigned)__cvta_generic_to_shared(s);
    asm volatile("cp.async.cg.shared.global [%0], [%1], 16;" :: "r"(sa), "l"(g));
}
__device__ __forceinline__ unsigned ld_acq(const unsigned* p) {
    unsigned v;
    asm volatile("ld.global.acquire.gpu.b32 %0, [%1];" : "=r"(v) : "l"(p));
    return v;
}

__global__ __launch_bounds__(RT2, 1) void gru_kernel(
    const float* __restrict__ gx,
    const float* __restrict__ W_hh,
    const float* __restrict__ b_hh)
{
    extern __shared__ float smem[];
    float* h_sh = smem;
    float* w_sh = smem + SM2_W;
    float* part = smem + SM2_PART;

    const int tid   = threadIdx.x;
    const int j0    = blockIdx.x * 4;
    const int warp  = tid >> 5, lane = tid & 31;
    const int kbase = warp * 64;

    // pack W_hh slice: w_sh[(k*3+g)*4+j] = W_hh[g*H + j0+j][k]
    for (int idx = tid; idx < 6144; idx += RT2) {
        int j = idx & 3;
        int g = (idx >> 2) % 3;
        int k = idx / 12;
        w_sh[idx] = W_hh[(size_t)(g * H_ + j0 + j) * H_ + k];
    }
    for (int idx = tid; idx < H_ * B_; idx += RT2) h_sh[idx] = 0.f;

    const int jj = tid >> 5, bb = tid & 31;   // gate-phase mapping (tid < 128)
    float bhr = 0.f, bhz = 0.f, bhn = 0.f;
    if (tid < 128) {
        bhr = b_hh[0 * H_ + j0 + jj];
        bhz = b_hh[1 * H_ + j0 + jj];
        bhn = b_hh[2 * H_ + j0 + jj];
    }
    __syncthreads();

    for (int t = 0; t < T_; ++t) {
        // ---- warp-local staging of this warp's K-slice (8KB) ----
        if (t > 0) {
            const float* src = g_hbuf[t & 1] + kbase * 32;
            float* dst = h_sh + kbase * 32;
#pragma unroll
            for (int i = 0; i < 16; ++i)
                cp_async16(dst + i * 128 + lane * 4, src + i * 128 + lane * 4);
            asm volatile("cp.async.commit_group;" ::: "memory");
        }
        // gx prefetch overlaps the cp.async flight time
        float gxr = 0.f, gxz = 0.f, gxn = 0.f;
        if (tid < 128) {
            const float* row = gx + ((size_t)bb * T_ + t) * G_;
            gxr = row[0 * H_ + j0 + jj];
            gxz = row[1 * H_ + j0 + jj];
            gxn = row[2 * H_ + j0 + jj];
        }
        if (t > 0) asm volatile("cp.async.wait_group 0;" ::: "memory");
        // no __syncthreads needed here: each warp computes only on its own slice

        // ---- 12 rows x 32 batch partials over k in [kbase, kbase+64) ----
        const float* hp = h_sh + kbase * 32 + lane;
        const float* wp = w_sh + kbase * 12;
        float acc[12];
#pragma unroll
        for (int i = 0; i < 12; ++i) acc[i] = 0.f;
#pragma unroll 8
        for (int k = 0; k < 64; ++k) {
            float hv = hp[k * 32];
            const float4* w4 = (const float4*)(wp + k * 12);
            float4 w0 = w4[0], w1 = w4[1], w2 = w4[2];
            acc[0]  = fmaf(hv, w0.x, acc[0]);
            acc[1]  = fmaf(hv, w0.y, acc[1]);
            acc[2]  = fmaf(hv, w0.z, acc[2]);
            acc[3]  = fmaf(hv, w0.w, acc[3]);
            acc[4]  = fmaf(hv, w1.x, acc[4]);
            acc[5]  = fmaf(hv, w1.y, acc[5]);
            acc[6]  = fmaf(hv, w1.z, acc[6]);
            acc[7]  = fmaf(hv, w1.w, acc[7]);
            acc[8]  = fmaf(hv, w2.x, acc[8]);
            acc[9]  = fmaf(hv, w2.y, acc[9]);
            acc[10] = fmaf(hv, w2.z, acc[10]);
            acc[11] = fmaf(hv, w2.w, acc[11]);
        }
        // part[((warp*3+g)*4+j)*32 + lane]
        {
            float* pp = part + (warp * 12) * 32 + lane;
#pragma unroll
            for (int i = 0; i < 12; ++i) pp[i * 32] = acc[i];
        }
        __syncthreads();

        // ---- gate math + h update (threads 0..127: one (j,b) each) ----
        if (tid < 128) {
            float sr = bhr, sz = bhz, sn = bhn;
#pragma unroll
            for (int w = 0; w < 8; ++w) {
                const float* pw = part + (w * 12) * 32 + bb;
                sr += pw[(0 * 4 + jj) * 32];
                sz += pw[(1 * 4 + jj) * 32];
                sn += pw[(2 * 4 + jj) * 32];
            }
            float hold = h_sh[(j0 + jj) * 32 + bb];
            float r  = 1.f / (1.f + expf(-(gxr + sr)));
            float z  = 1.f / (1.f + expf(-(gxz + sz)));
            float n  = tanhf(gxn + r * sn);
            float hn = (1.f - z) * n + z * hold;
            g_hbuf[(t + 1) & 1][(j0 + jj) * 32 + bb] = hn;
            g_hs[((size_t)bb * T_ + t) * H_ + j0 + jj] = hn;
        }

        // ---- grid barrier (release/acquire, pure spin) ----
        __syncthreads();
        if (tid == 0) {
            unsigned old = ld_acq(&g_gen);
            __threadfence();                       // h writes visible before arrival
            unsigned tick = atomicAdd(&g_cnt, 1u);
            if (tick == NBLK - 1) {
                atomicExch(&g_cnt, 0u);
                __threadfence();
                atomicExch(&g_gen, old + 1u);
            } else {
                while (ld_acq(&g_gen) == old) { }
            }
        }
        __syncthreads();
    }
}

// ==============================================================================
// In-place log_softmax over V=41 columns; one warp per row.
// ==============================================================================
__global__ __launch_bounds__(256) void lsm_kernel(float* __restrict__ out, int Mrows)
{
    int row  = blockIdx.x * 8 + (threadIdx.x >> 5);
    int lane = threadIdx.x & 31;
    if (row >= Mrows) return;
    float* p = out + (size_t)row * V_;

    float v0 = (lane      < V_) ? p[lane]      : -INFINITY;
    float v1 = (lane + 32 < V_) ? p[lane + 32] : -INFINITY;
    float m = fmaxf(v0, v1);
#pragma unroll
    for (int o = 16; o > 0; o >>= 1) m = fmaxf(m, __shfl_xor_sync(0xFFFFFFFFu, m, o));
    float s = 0.f;
    if (lane      < V_) s += expf(v0 - m);
    if (lane + 32 < V_) s += expf(v1 - m);
#pragma unroll
    for (int o = 16; o > 0; o >>= 1) s += __shfl_xor_sync(0xFFFFFFFFu, s, o);
    float l = m + logf(s);
    if (lane      < V_) p[lane]      = v0 - l;
    if (lane + 32 < V_) p[lane + 32] = v1 - l;
}

// ==============================================================================
// Host launcher
// ==============================================================================
extern "C" void kernel_launch(void* const* d_in, const int* in_sizes, int n_in,
                              void* d_out, int out_size)
{
    const float* x     = (const float*)d_in[0];
    const float* W_ad  = (const float*)d_in[1];
    const float* b_ad  = (const float*)d_in[2];
    const float* W_ih  = (const float*)d_in[3];
    const float* W_hh  = (const float*)d_in[4];
    const float* b_ih  = (const float*)d_in[5];
    const float* b_hh  = (const float*)d_in[6];
    const float* W_fc  = (const float*)d_in[7];
    const float* b_fc  = (const float*)d_in[8];
    float* out = (float*)d_out;

    float *pa, *pgx, *phs;
    cudaGetSymbolAddress((void**)&pa,  g_a);
    cudaGetSymbolAddress((void**)&pgx, g_gx);
    cudaGetSymbolAddress((void**)&phs, g_hs);

    cudaFuncSetAttribute(gru_kernel, cudaFuncAttributeMaxDynamicSharedMemorySize,
                         SMEM2_BYTES);

    // 1) adapter: a = x @ W_ad^T + b_ad        (M x 256, K=512)
    gemm_bias_kernel<<<dim3(A_ / GBN, M_ / GBM), 256>>>(x, W_ad, b_ad, pa, M_, A_, DIN_);
    // 2) gates:   gx = a @ W_ih^T + b_ih       (M x 1536, K=256)
    gemm_bias_kernel<<<dim3(G_ / GBN, M_ / GBM), 256>>>(pa, W_ih, b_ih, pgx, M_, G_, A_);
    // 3) GRU recurrence (persistent, grid barrier per step)
    gru_kernel<<<NBLK, RT2, SMEM2_BYTES>>>(pgx, W_hh, b_hh);
    // 4) logits into d_out: hs @ W_fc^T + b_fc (M x 41, K=512)
    gemm_bias_kernel<<<dim3(1, M_ / GBM), 256>>>(phs, W_fc, b_fc, out, M_, V_, H_);
    // 5) in-place log_softmax
    lsm_kernel<<<M_ / 8, 256>>>(out, M_);
}